// round 4
// baseline (speedup 1.0000x reference)
#include <cuda_runtime.h>
#include <math.h>

#define N_NODES 50000
#define N_EDGES 800000
#define DIM 512
#define SCALE_OFF ((size_t)N_NODES * DIM)

// Scratch: aggregated neighbor features (sum over incoming edges). ~100 MB.
__device__ float g_agg[(size_t)N_NODES * DIM];
// 1 if edge_index buffer is int64, 0 if int32. Set by detect kernel each call.
__device__ int g_idx64;

// ---------------------------------------------------------------------------
// Detect edge_index dtype. int32 data viewed as int64 packs two indices into
// one word -> values far outside [0, N_NODES). Reads 512 bytes (buffer >= 6.4MB).
// ---------------------------------------------------------------------------
__global__ void detect_idx_kernel(const void* __restrict__ ei) {
    if (threadIdx.x == 0 && blockIdx.x == 0) {
        const long long* p = (const long long*)ei;
        int is64 = 1;
        for (int i = 0; i < 64; i++) {
            long long v = p[i];
            if (v < 0 || v >= N_NODES) { is64 = 0; break; }
        }
        g_idx64 = is64;
    }
}

// ---------------------------------------------------------------------------
// Zero the aggregation buffer (float4 stores, exact coverage)
// ---------------------------------------------------------------------------
__global__ void __launch_bounds__(256) zero_agg_kernel() {
    size_t i = (size_t)blockIdx.x * blockDim.x + threadIdx.x;   // float4 index
    ((float4*)g_agg)[i] = make_float4(0.f, 0.f, 0.f, 0.f);
}

// ---------------------------------------------------------------------------
// Edge scatter: one warp per edge. agg[dst] += x[src], float4 atomics.
// ---------------------------------------------------------------------------
__global__ void __launch_bounds__(256) scatter_add_kernel(
    const float* __restrict__ x, const void* __restrict__ ei)
{
    int warp = (blockIdx.x * blockDim.x + threadIdx.x) >> 5;
    int lane = threadIdx.x & 31;
    if (warp >= N_EDGES) return;

    int s, d;
    if (g_idx64) {
        const long long* p = (const long long*)ei;
        s = (int)p[warp];
        d = (int)p[N_EDGES + warp];
    } else {
        const int* p = (const int*)ei;
        s = p[warp];
        d = p[N_EDGES + warp];
    }
    if ((unsigned)s >= N_NODES || (unsigned)d >= N_NODES) return;  // safety net

    const float4* xs = (const float4*)(x + (size_t)s * DIM);
    float4* ag = (float4*)(g_agg + (size_t)d * DIM);
#pragma unroll
    for (int i = 0; i < 4; i++) {
        int c = lane + i * 32;          // float4 index 0..127
        float4 v = __ldg(xs + c);
        atomicAdd(ag + c, v);           // sm_90+ 128-bit red.global.add.v4.f32
    }
}

// ---------------------------------------------------------------------------
// Fused GEMM + epilogue.
//   A[n,k] = (k < 512) ? agg[n,k] : x[n,k-512]           (M=50000, K=1024)
//   B[j,k]: quadrant select over (Wl1,Wr1,Wl2,Wr2)       (N=1024)
//   C[n,j<512]  -> loc   = clip(. + bl1, -100, 100)
//   C[n,j>=512] -> scale = min(softplus(. + bl2) + 1e-3, 100)
// 128x128 block tile, BK=16, 256 threads, 8x8 register tile,
// inner product via packed fma.rn.f32x2 (Blackwell FFMA2).
// ---------------------------------------------------------------------------
#define BM 128
#define BN 128
#define BK 16
#define PAD 132

typedef unsigned long long ull;

__device__ __forceinline__ ull pack2(float lo, float hi) {
    ull r;
    asm("mov.b64 %0, {%1, %2};" : "=l"(r) : "f"(lo), "f"(hi));
    return r;
}
__device__ __forceinline__ void fma2(ull& d, ull a, ull b) {
    asm("fma.rn.f32x2 %0, %1, %2, %0;" : "+l"(d) : "l"(a), "l"(b));
}

__global__ void __launch_bounds__(256) fused_gemm_kernel(
    const float* __restrict__ x,
    const float* __restrict__ Wl1, const float* __restrict__ bl1,
    const float* __restrict__ Wr1,
    const float* __restrict__ Wl2, const float* __restrict__ bl2,
    const float* __restrict__ Wr2,
    float* __restrict__ out)
{
    __shared__ float As[BK][PAD];
    __shared__ float Bs[BK][PAD];

    const int tid = threadIdx.x;
    const int m0  = blockIdx.y * BM;
    const int n0  = blockIdx.x * BN;

    const int tm = (tid >> 4) * 8;       // 0..120
    const int tn = (tid & 15) * 8;       // 0..120

    const int ldRow = tid >> 2;          // 0..63
    const int ldCol = (tid & 3) * 4;     // 0,4,8,12

    const bool isScale = (n0 >= 512);
    const float* Bk0 = isScale ? Wl2 : Wl1;   // k in [0,512)
    const float* Bk1 = isScale ? Wr2 : Wr1;   // k in [512,1024)
    const int nLoc = n0 & 511;

    ull acc[8][4];                        // 8 M-rows x 4 packed N-pairs
#pragma unroll
    for (int i = 0; i < 8; i++)
#pragma unroll
        for (int p = 0; p < 4; p++) acc[i][p] = 0ull;

    for (int kt = 0; kt < 64; ++kt) {
        const int k0 = kt * BK;
        const int kl = k0 & 511;
        const float* Asrc = (k0 < 512) ? g_agg : x;
        const float* Bsrc = (k0 < 512) ? Bk0 : Bk1;

#pragma unroll
        for (int h = 0; h < 2; ++h) {
            int m = m0 + ldRow + h * 64;
            float4 v = make_float4(0.f, 0.f, 0.f, 0.f);
            if (m < N_NODES)
                v = *(const float4*)(Asrc + (size_t)m * 512 + kl + ldCol);
            As[ldCol + 0][ldRow + h * 64] = v.x;
            As[ldCol + 1][ldRow + h * 64] = v.y;
            As[ldCol + 2][ldRow + h * 64] = v.z;
            As[ldCol + 3][ldRow + h * 64] = v.w;
        }
#pragma unroll
        for (int h = 0; h < 2; ++h) {
            int j = nLoc + ldRow + h * 64;
            float4 v = *(const float4*)(Bsrc + (size_t)j * 512 + kl + ldCol);
            Bs[ldCol + 0][ldRow + h * 64] = v.x;
            Bs[ldCol + 1][ldRow + h * 64] = v.y;
            Bs[ldCol + 2][ldRow + h * 64] = v.z;
            Bs[ldCol + 3][ldRow + h * 64] = v.w;
        }
        __syncthreads();

#pragma unroll
        for (int k = 0; k < BK; ++k) {
            float rM[8];
            *(float4*)&rM[0] = *(const float4*)&As[k][tm];
            *(float4*)&rM[4] = *(const float4*)&As[k][tm + 4];
            ull rN[4];                       // packed pairs straight from smem
            rN[0] = *(const ull*)&Bs[k][tn + 0];
            rN[1] = *(const ull*)&Bs[k][tn + 2];
            rN[2] = *(const ull*)&Bs[k][tn + 4];
            rN[3] = *(const ull*)&Bs[k][tn + 6];
#pragma unroll
            for (int i = 0; i < 8; i++) {
                ull a2 = pack2(rM[i], rM[i]);
#pragma unroll
                for (int p = 0; p < 4; p++)
                    fma2(acc[i][p], a2, rN[p]);
            }
        }
        __syncthreads();
    }

    // Epilogue
    const float* bias = isScale ? bl2 : bl1;
#pragma unroll
    for (int i = 0; i < 8; i++) {
        int m = m0 + tm + i;
        if (m >= N_NODES) break;
#pragma unroll
        for (int p = 0; p < 4; p++) {
#pragma unroll
            for (int h = 0; h < 2; h++) {
                int j = 2 * p + h;
                unsigned bits = (h == 0) ? (unsigned)(acc[i][p] & 0xFFFFFFFFull)
                                         : (unsigned)(acc[i][p] >> 32);
                int jg = nLoc + tn + j;            // local column in half (0..511)
                float v = __uint_as_float(bits) + bias[jg];
                if (!isScale) {
                    v = fminf(fmaxf(v, -100.f), 100.f);
                    out[(size_t)m * DIM + jg] = v;
                } else {
                    float sp = fmaxf(v, 0.f) + log1pf(expf(-fabsf(v)));
                    sp = fminf(sp + 0.001f, 100.f);
                    out[SCALE_OFF + (size_t)m * DIM + jg] = sp;
                }
            }
        }
    }
}

// ---------------------------------------------------------------------------
extern "C" void kernel_launch(void* const* d_in, const int* in_sizes, int n_in,
                              void* d_out, int out_size)
{
    // Identify inputs by element count (robust to ordering schema).
    const float* x = 0;
    const void*  ei = 0;
    const float* Ws[4]; int nW = 0; int wpos[4];
    const float* bs[2]; int nb = 0; int bpos[2];
    for (int i = 0; i < n_in; i++) {
        int sz = in_sizes[i];
        if (sz == N_NODES * DIM)            x = (const float*)d_in[i];
        else if (sz == 2 * N_EDGES)         ei = d_in[i];
        else if (sz == DIM * DIM) { if (nW < 4) { wpos[nW] = i; Ws[nW++] = (const float*)d_in[i]; } }
        else if (sz == DIM)       { if (nb < 2) { bpos[nb] = i; bs[nb++] = (const float*)d_in[i]; } }
    }

    const float *Wl1, *Wr1, *Wl2, *Wr2, *bl1, *bl2;
    bl1 = bs[0]; bl2 = bs[1];
    if (nb == 2 && nW == 4 && bpos[0] < wpos[1]) {
        // dict order: Wl1, bl1, Wr1, Wl2, bl2, Wr2
        Wl1 = Ws[0]; Wr1 = Ws[1]; Wl2 = Ws[2]; Wr2 = Ws[3];
    } else {
        // alphabetical: Wl1, Wl2, Wr1, Wr2, bl1, bl2
        Wl1 = Ws[0]; Wl2 = Ws[1]; Wr1 = Ws[2]; Wr2 = Ws[3];
    }
    float* out = (float*)d_out;

    detect_idx_kernel<<<1, 32>>>(ei);
    // 50000*512/4 float4 = 6,400,000 -> 25000 blocks x 256 threads
    zero_agg_kernel<<<25000, 256>>>();
    // 800000 warps -> 100000 blocks x 8 warps
    scatter_add_kernel<<<100000, 256>>>(x, ei);
    // grid: 8 N-tiles x 391 M-tiles
    fused_gemm_kernel<<<dim3(8, 391), 256>>>(x, Wl1, bl1, Wr1, Wl2, bl2, Wr2, out);
}

// round 6
// speedup vs baseline: 1.9900x; 1.9900x over previous
#include <cuda_runtime.h>
#include <cuda_bf16.h>
#include <math.h>
#include <stdint.h>

#define N_NODES 50000
#define N_EDGES 800000
#define DIM 512
#define KTOT 1024
#define SCALE_OFF ((size_t)N_NODES * DIM)
#define M_PAD 50048                      // 391 * 128

// ---------------- scratch (__device__ globals; no allocation allowed) -------
__device__ float g_agg[(size_t)N_NODES * DIM];                 // 102 MB
__device__ __nv_bfloat16 g_Ahi[(size_t)M_PAD * KTOT];          // 102 MB
__device__ __nv_bfloat16 g_Alo[(size_t)M_PAD * KTOT];          // 102 MB
__device__ __nv_bfloat16 g_Bhi[(size_t)KTOT * KTOT];           // 2 MB
__device__ __nv_bfloat16 g_Blo[(size_t)KTOT * KTOT];           // 2 MB
__device__ int g_idx64;

// ---------------- PTX helpers (all non-'a' features: sm_80-level) -----------
__device__ __forceinline__ uint32_t smem_u32(const void* p) {
    uint32_t a;
    asm("{ .reg .u64 t; cvta.to.shared.u64 t, %1; cvt.u32.u64 %0, t; }" : "=r"(a) : "l"(p));
    return a;
}
__device__ __forceinline__ void cp16(uint32_t saddr, const void* g) {
    asm volatile("cp.async.cg.shared.global [%0], [%1], 16;" :: "r"(saddr), "l"(g));
}
__device__ __forceinline__ void cp_commit() {
    asm volatile("cp.async.commit_group;" ::: "memory");
}
template <int N>
__device__ __forceinline__ void cp_wait() {
    asm volatile("cp.async.wait_group %0;" :: "n"(N) : "memory");
}
__device__ __forceinline__ void ldsm4(uint32_t* r, uint32_t addr) {
    asm volatile("ldmatrix.sync.aligned.m8n8.x4.shared.b16 {%0,%1,%2,%3}, [%4];"
        : "=r"(r[0]), "=r"(r[1]), "=r"(r[2]), "=r"(r[3]) : "r"(addr));
}
__device__ __forceinline__ void mma_bf16(float* c, const uint32_t* a, const uint32_t* b) {
    asm volatile("mma.sync.aligned.m16n8k16.row.col.f32.bf16.bf16.f32 "
        "{%0,%1,%2,%3}, {%4,%5,%6,%7}, {%8,%9}, {%0,%1,%2,%3};"
        : "+f"(c[0]), "+f"(c[1]), "+f"(c[2]), "+f"(c[3])
        : "r"(a[0]), "r"(a[1]), "r"(a[2]), "r"(a[3]), "r"(b[0]), "r"(b[1]));
}

// ---------------------------------------------------------------------------
__global__ void detect_idx_kernel(const void* __restrict__ ei) {
    if (threadIdx.x == 0 && blockIdx.x == 0) {
        const long long* p = (const long long*)ei;
        int is64 = 1;
        for (int i = 0; i < 64; i++) {
            long long v = p[i];
            if (v < 0 || v >= N_NODES) { is64 = 0; break; }
        }
        g_idx64 = is64;
    }
}

__global__ void __launch_bounds__(256) zero_agg_kernel() {
    size_t i = (size_t)blockIdx.x * blockDim.x + threadIdx.x;
    ((float4*)g_agg)[i] = make_float4(0.f, 0.f, 0.f, 0.f);
}

__global__ void __launch_bounds__(256) scatter_add_kernel(
    const float* __restrict__ x, const void* __restrict__ ei)
{
    int warp = (blockIdx.x * blockDim.x + threadIdx.x) >> 5;
    int lane = threadIdx.x & 31;
    if (warp >= N_EDGES) return;
    int s, d;
    if (g_idx64) {
        const long long* p = (const long long*)ei;
        s = (int)p[warp]; d = (int)p[N_EDGES + warp];
    } else {
        const int* p = (const int*)ei;
        s = p[warp]; d = p[N_EDGES + warp];
    }
    if ((unsigned)s >= N_NODES || (unsigned)d >= N_NODES) return;
    const float4* xs = (const float4*)(x + (size_t)s * DIM);
    float4* ag = (float4*)(g_agg + (size_t)d * DIM);
#pragma unroll
    for (int i = 0; i < 4; i++) {
        float4 v = __ldg(xs + lane + i * 32);
        atomicAdd(ag + lane + i * 32, v);
    }
}

// A = [agg | x] (row-major, K=1024), split into bf16 hi/lo. Pads rows>=50000.
__global__ void __launch_bounds__(256) convertA_kernel(const float* __restrict__ x) {
    int row = blockIdx.x;                    // 0..M_PAD-1
    int c4  = threadIdx.x * 4;               // 0..1020
    float4 v = make_float4(0.f, 0.f, 0.f, 0.f);
    if (row < N_NODES) {
        const float* src = (c4 < 512) ? g_agg : x;
        v = *(const float4*)(src + (size_t)row * DIM + (c4 & 511));
    }
    __nv_bfloat16 h0 = __float2bfloat16(v.x), h1 = __float2bfloat16(v.y);
    __nv_bfloat16 h2 = __float2bfloat16(v.z), h3 = __float2bfloat16(v.w);
    __nv_bfloat16 l0 = __float2bfloat16(v.x - __bfloat162float(h0));
    __nv_bfloat16 l1 = __float2bfloat16(v.y - __bfloat162float(h1));
    __nv_bfloat16 l2 = __float2bfloat16(v.z - __bfloat162float(h2));
    __nv_bfloat16 l3 = __float2bfloat16(v.w - __bfloat162float(h3));
    size_t o = (size_t)row * KTOT + c4;
    __nv_bfloat162 hA = {h0, h1}, hB = {h2, h3}, lA = {l0, l1}, lB = {l2, l3};
    *(uint2*)(g_Ahi + o) = make_uint2(*(uint32_t*)&hA, *(uint32_t*)&hB);
    *(uint2*)(g_Alo + o) = make_uint2(*(uint32_t*)&lA, *(uint32_t*)&lB);
}

// B[n][k]: n<512 -> [Wl1 | Wr1], n>=512 -> [Wl2 | Wr2]
__global__ void __launch_bounds__(256) convertB_kernel(
    const float* __restrict__ Wl1, const float* __restrict__ Wr1,
    const float* __restrict__ Wl2, const float* __restrict__ Wr2)
{
    int n  = blockIdx.x;                     // 0..1023
    int c4 = threadIdx.x * 4;
    const float* src = (n < 512) ? ((c4 < 512) ? Wl1 : Wr1)
                                 : ((c4 < 512) ? Wl2 : Wr2);
    float4 v = *(const float4*)(src + (size_t)(n & 511) * DIM + (c4 & 511));
    __nv_bfloat16 h0 = __float2bfloat16(v.x), h1 = __float2bfloat16(v.y);
    __nv_bfloat16 h2 = __float2bfloat16(v.z), h3 = __float2bfloat16(v.w);
    __nv_bfloat16 l0 = __float2bfloat16(v.x - __bfloat162float(h0));
    __nv_bfloat16 l1 = __float2bfloat16(v.y - __bfloat162float(h1));
    __nv_bfloat16 l2 = __float2bfloat16(v.z - __bfloat162float(h2));
    __nv_bfloat16 l3 = __float2bfloat16(v.w - __bfloat162float(h3));
    size_t o = (size_t)n * KTOT + c4;
    __nv_bfloat162 hA = {h0, h1}, hB = {h2, h3}, lA = {l0, l1}, lB = {l2, l3};
    *(uint2*)(g_Bhi + o) = make_uint2(*(uint32_t*)&hA, *(uint32_t*)&hB);
    *(uint2*)(g_Blo + o) = make_uint2(*(uint32_t*)&lA, *(uint32_t*)&lB);
}

// ---------------------------------------------------------------------------
// mma.sync GEMM: 128x128 CTA tile, BK=32, double-buffered cp.async.
// 8 warps, warp tile 64x32 (m16n8k16 x 4m x 4n x 2k).
// Split precision: D += Ahi*Bhi + Alo*Bhi + Ahi*Blo.
// smem rows padded to 80B (bank-conflict-free ldmatrix).
// ---------------------------------------------------------------------------
#define BK 32
#define AROW 80
#define TILE_SM (128 * AROW)            // 10240 B
#define BUF_SZ (4 * TILE_SM)            // 40960 B
#define SMEM_DYN (2 * BUF_SZ)           // 81920 B

__global__ void __launch_bounds__(256)
gemm_mma_kernel(const float* __restrict__ bl1, const float* __restrict__ bl2,
                float* __restrict__ out)
{
    extern __shared__ __align__(16) char dsmem[];
    __shared__ float bias_s[128];

    const int tid  = threadIdx.x;
    const int wid  = tid >> 5;
    const int lane = tid & 31;
    const int m0   = blockIdx.y * 128;
    const int n0   = blockIdx.x * 128;
    const bool isScale = (n0 >= 512);
    const int nLoc = n0 & 511;

    if (tid < 128) bias_s[tid] = (isScale ? bl2 : bl1)[nLoc + tid];

    const uint32_t sbase = smem_u32(dsmem);
    const __nv_bfloat16* srcs[4] = {
        g_Ahi + (size_t)m0 * KTOT, g_Alo + (size_t)m0 * KTOT,
        g_Bhi + (size_t)n0 * KTOT, g_Blo + (size_t)n0 * KTOT };

    // ---- async stage loader: 4 tiles x 128 rows x 64B, 16B chunks ----------
    auto load_stage = [&](int kt, int buf) {
        const int k0 = kt * BK;
        uint32_t bbase = sbase + buf * BUF_SZ;
#pragma unroll
        for (int i = 0; i < 8; ++i) {
            int t   = i >> 1;
            int idx = tid + ((i & 1) << 8);     // 0..511
            int row = idx >> 2;
            int c16 = idx & 3;
            const void* g = srcs[t] + (size_t)row * KTOT + k0 + c16 * 8;
            cp16(bbase + t * TILE_SM + row * AROW + c16 * 16, g);
        }
        cp_commit();
    };

    const int mw = (wid & 1) * 64;      // warp M offset
    const int nw = (wid >> 1) * 32;     // warp N offset

    float acc[4][4][4];
#pragma unroll
    for (int mt = 0; mt < 4; mt++)
#pragma unroll
        for (int nt = 0; nt < 4; nt++)
#pragma unroll
            for (int r = 0; r < 4; r++) acc[mt][nt][r] = 0.f;

    load_stage(0, 0);

    for (int kt = 0; kt < KTOT / BK; ++kt) {
        if (kt + 1 < KTOT / BK) { load_stage(kt + 1, (kt + 1) & 1); cp_wait<1>(); }
        else cp_wait<0>();
        __syncthreads();

        const uint32_t bbase = sbase + (kt & 1) * BUF_SZ;
        // per-thread ldmatrix address components
        const int aRowOff = (lane & 15);                 // + mtile base
        const int aColB   = (lane >> 4) << 4;            // 0 or 16 bytes (k half)
        const int bRowOff = (lane & 7) + ((lane >> 4) << 3);
        const int bColB   = ((lane >> 3) & 1) << 4;      // 0 or 16 bytes

#pragma unroll
        for (int ks = 0; ks < 2; ++ks) {
            const int kb = ks * 32;                      // byte offset of k-step
            uint32_t ahi[4][4], alo[4][4], bhi[2][4], blo[2][4];
#pragma unroll
            for (int mt = 0; mt < 4; mt++) {
                uint32_t ra = bbase + (mw + mt * 16 + aRowOff) * AROW + kb + aColB;
                ldsm4(ahi[mt], ra);
                ldsm4(alo[mt], ra + TILE_SM);
            }
#pragma unroll
            for (int np = 0; np < 2; np++) {
                uint32_t rb = bbase + 2 * TILE_SM
                            + (nw + np * 16 + bRowOff) * AROW + kb + bColB;
                ldsm4(bhi[np], rb);
                ldsm4(blo[np], rb + TILE_SM);
            }
#pragma unroll
            for (int mt = 0; mt < 4; mt++)
#pragma unroll
                for (int nt = 0; nt < 4; nt++) {
                    const uint32_t* bh = &bhi[nt >> 1][(nt & 1) * 2];
                    const uint32_t* bl = &blo[nt >> 1][(nt & 1) * 2];
                    mma_bf16(acc[mt][nt], ahi[mt], bh);
                    mma_bf16(acc[mt][nt], alo[mt], bh);
                    mma_bf16(acc[mt][nt], ahi[mt], bl);
                }
        }
        __syncthreads();
    }

    // ---- epilogue -----------------------------------------------------------
    const int rq = lane >> 2;            // 0..7
    const int cq = (lane & 3) * 2;       // 0,2,4,6
#pragma unroll
    for (int mt = 0; mt < 4; mt++) {
        int r0 = m0 + mw + mt * 16 + rq;
#pragma unroll
        for (int half = 0; half < 2; half++) {
            int m = r0 + half * 8;
            if (m >= N_NODES) continue;
            float* op = out + (isScale ? SCALE_OFF : 0) + (size_t)m * DIM + nLoc;
#pragma unroll
            for (int nt = 0; nt < 4; nt++) {
                int cl = nw + nt * 8 + cq;
                float v0 = acc[mt][nt][half * 2 + 0] + bias_s[cl];
                float v1 = acc[mt][nt][half * 2 + 1] + bias_s[cl + 1];
                if (!isScale) {
                    v0 = fminf(fmaxf(v0, -100.f), 100.f);
                    v1 = fminf(fmaxf(v1, -100.f), 100.f);
                } else {
                    v0 = fminf(fmaxf(v0, 0.f) + log1pf(expf(-fabsf(v0))) + 0.001f, 100.f);
                    v1 = fminf(fmaxf(v1, 0.f) + log1pf(expf(-fabsf(v1))) + 0.001f, 100.f);
                }
                *(float2*)(op + cl) = make_float2(v0, v1);
            }
        }
    }
}

// ---------------------------------------------------------------------------
extern "C" void kernel_launch(void* const* d_in, const int* in_sizes, int n_in,
                              void* d_out, int out_size)
{
    const float* x = 0;
    const void*  ei = 0;
    const float* Ws[4]; int nW = 0; int wpos[4];
    const float* bs[2]; int nb = 0; int bpos[2];
    for (int i = 0; i < n_in; i++) {
        int sz = in_sizes[i];
        if (sz == N_NODES * DIM)      x = (const float*)d_in[i];
        else if (sz == 2 * N_EDGES)   ei = d_in[i];
        else if (sz == DIM * DIM) { if (nW < 4) { wpos[nW] = i; Ws[nW++] = (const float*)d_in[i]; } }
        else if (sz == DIM)       { if (nb < 2) { bpos[nb] = i; bs[nb++] = (const float*)d_in[i]; } }
    }
    const float *Wl1, *Wr1, *Wl2, *Wr2, *bl1, *bl2;
    bl1 = bs[0]; bl2 = bs[1];
    if (nb == 2 && nW == 4 && bpos[0] < wpos[1]) {
        Wl1 = Ws[0]; Wr1 = Ws[1]; Wl2 = Ws[2]; Wr2 = Ws[3];   // dict order
    } else {
        Wl1 = Ws[0]; Wl2 = Ws[1]; Wr1 = Ws[2]; Wr2 = Ws[3];   // alphabetical
    }
    float* out = (float*)d_out;

    static int smem_set = 0;
    if (!smem_set) {
        cudaFuncSetAttribute(gemm_mma_kernel,
                             cudaFuncAttributeMaxDynamicSharedMemorySize, SMEM_DYN);
        smem_set = 1;
    }

    detect_idx_kernel<<<1, 32>>>(ei);
    zero_agg_kernel<<<25000, 256>>>();
    scatter_add_kernel<<<100000, 256>>>(x, ei);
    convertA_kernel<<<M_PAD, 256>>>(x);
    convertB_kernel<<<1024, 256>>>(Wl1, Wr1, Wl2, Wr2);
    gemm_mma_kernel<<<dim3(8, 391), 256, SMEM_DYN>>>(bl1, bl2, out);
}

// round 9
// speedup vs baseline: 2.3220x; 1.1668x over previous
#include <cuda_runtime.h>
#include <cuda_bf16.h>
#include <math.h>
#include <stdint.h>

#define N_NODES 50000
#define N_EDGES 800000
#define DIM 512
#define KTOT 1024
#define SCALE_OFF ((size_t)N_NODES * DIM)
#define M_PAD 50048                      // 391 * 128
#define NSCAN_BLK 98                     // ceil(50000/512)

// ---------------- scratch (__device__ globals) ------------------------------
__device__ __nv_bfloat16 g_Ahi[(size_t)M_PAD * KTOT];          // 102 MB
__device__ __nv_bfloat16 g_Alo[(size_t)M_PAD * KTOT];          // 102 MB
__device__ __nv_bfloat16 g_Bhi[(size_t)KTOT * KTOT];           // 2 MB
__device__ __nv_bfloat16 g_Blo[(size_t)KTOT * KTOT];           // 2 MB
__device__ int g_deg[N_NODES];
__device__ int g_ptr[N_NODES];
__device__ int g_cursor[N_NODES];
__device__ int g_bsum[NSCAN_BLK];
__device__ int g_boff[NSCAN_BLK];
__device__ int g_csr[N_EDGES];
__device__ int g_idx64;

// ---------------- PTX helpers (sm_80-level only; no 'a' features) -----------
__device__ __forceinline__ uint32_t smem_u32(const void* p) {
    uint32_t a;
    asm("{ .reg .u64 t; cvta.to.shared.u64 t, %1; cvt.u32.u64 %0, t; }" : "=r"(a) : "l"(p));
    return a;
}
__device__ __forceinline__ void cp16(uint32_t saddr, const void* g) {
    asm volatile("cp.async.cg.shared.global [%0], [%1], 16;" :: "r"(saddr), "l"(g));
}
__device__ __forceinline__ void cp_commit() {
    asm volatile("cp.async.commit_group;" ::: "memory");
}
template <int N>
__device__ __forceinline__ void cp_wait() {
    asm volatile("cp.async.wait_group %0;" :: "n"(N) : "memory");
}
__device__ __forceinline__ void ldsm4(uint32_t* r, uint32_t addr) {
    asm volatile("ldmatrix.sync.aligned.m8n8.x4.shared.b16 {%0,%1,%2,%3}, [%4];"
        : "=r"(r[0]), "=r"(r[1]), "=r"(r[2]), "=r"(r[3]) : "r"(addr));
}
__device__ __forceinline__ void mma_bf16(float* c, const uint32_t* a, const uint32_t* b) {
    asm volatile("mma.sync.aligned.m16n8k16.row.col.f32.bf16.bf16.f32 "
        "{%0,%1,%2,%3}, {%4,%5,%6,%7}, {%8,%9}, {%0,%1,%2,%3};"
        : "+f"(c[0]), "+f"(c[1]), "+f"(c[2]), "+f"(c[3])
        : "r"(a[0]), "r"(a[1]), "r"(a[2]), "r"(a[3]), "r"(b[0]), "r"(b[1]));
}

// ---------------------------------------------------------------------------
__global__ void detect_idx_kernel(const void* __restrict__ ei) {
    if (threadIdx.x == 0 && blockIdx.x == 0) {
        const long long* p = (const long long*)ei;
        int is64 = 1;
        for (int i = 0; i < 64; i++) {
            long long v = p[i];
            if (v < 0 || v >= N_NODES) { is64 = 0; break; }
        }
        g_idx64 = is64;
    }
}

__global__ void __launch_bounds__(1024) zero_deg_kernel() {
    int i = blockIdx.x * 1024 + threadIdx.x;
    if (i < N_NODES) g_deg[i] = 0;
}

__global__ void __launch_bounds__(256) hist_kernel(const void* __restrict__ ei) {
    int e = blockIdx.x * blockDim.x + threadIdx.x;
    if (e >= N_EDGES) return;
    int d = g_idx64 ? (int)((const long long*)ei)[N_EDGES + e]
                    : ((const int*)ei)[N_EDGES + e];
    if ((unsigned)d < N_NODES) atomicAdd(&g_deg[d], 1);
}

// Block-wise exclusive scan of g_deg (512/block); block sums to g_bsum.
__global__ void __launch_bounds__(512) scan1_kernel() {
    __shared__ int sm[512];
    int b = blockIdx.x, t = threadIdx.x;
    int i = b * 512 + t;
    int v = (i < N_NODES) ? g_deg[i] : 0;
    sm[t] = v;
    __syncthreads();
#pragma unroll
    for (int off = 1; off < 512; off <<= 1) {
        int u = (t >= off) ? sm[t - off] : 0;
        __syncthreads();
        sm[t] += u;
        __syncthreads();
    }
    if (i < N_NODES) g_ptr[i] = sm[t] - v;        // exclusive within block
    if (t == 511) g_bsum[b] = sm[511];
}

__global__ void scan2_kernel() {
    if (threadIdx.x == 0 && blockIdx.x == 0) {
        int run = 0;
        for (int b = 0; b < NSCAN_BLK; b++) { g_boff[b] = run; run += g_bsum[b]; }
    }
}

__global__ void __launch_bounds__(512) scan3_kernel() {
    int i = blockIdx.x * 512 + threadIdx.x;
    if (i < N_NODES) {
        int v = g_ptr[i] + g_boff[i >> 9];
        g_ptr[i] = v;
        g_cursor[i] = v;
    }
}

__global__ void __launch_bounds__(256) fill_kernel(const void* __restrict__ ei) {
    int e = blockIdx.x * blockDim.x + threadIdx.x;
    if (e >= N_EDGES) return;
    int s, d;
    if (g_idx64) {
        const long long* p = (const long long*)ei;
        s = (int)p[e]; d = (int)p[N_EDGES + e];
    } else {
        const int* p = (const int*)ei;
        s = p[e]; d = p[N_EDGES + e];
    }
    if ((unsigned)s >= N_NODES || (unsigned)d >= N_NODES) return;
    int pos = atomicAdd(&g_cursor[d], 1);
    g_csr[pos] = s;
}

// ---------------------------------------------------------------------------
// Aggregate (CSR, register accumulation) + fused bf16 hi/lo split of
// A = [agg | x]. One block (128 thr) per padded row; thread owns 4 floats.
// ---------------------------------------------------------------------------
__device__ __forceinline__ void split_store(float4 v, size_t o) {
    __nv_bfloat16 h0 = __float2bfloat16(v.x), h1 = __float2bfloat16(v.y);
    __nv_bfloat16 h2 = __float2bfloat16(v.z), h3 = __float2bfloat16(v.w);
    __nv_bfloat16 l0 = __float2bfloat16(v.x - __bfloat162float(h0));
    __nv_bfloat16 l1 = __float2bfloat16(v.y - __bfloat162float(h1));
    __nv_bfloat16 l2 = __float2bfloat16(v.z - __bfloat162float(h2));
    __nv_bfloat16 l3 = __float2bfloat16(v.w - __bfloat162float(h3));
    __nv_bfloat162 hA = {h0, h1}, hB = {h2, h3}, lA = {l0, l1}, lB = {l2, l3};
    *(uint2*)(g_Ahi + o) = make_uint2(*(uint32_t*)&hA, *(uint32_t*)&hB);
    *(uint2*)(g_Alo + o) = make_uint2(*(uint32_t*)&lA, *(uint32_t*)&lB);
}

__global__ void __launch_bounds__(128) agg_convert_kernel(const float* __restrict__ x) {
    int row = blockIdx.x;                       // 0..M_PAD-1
    int c4  = threadIdx.x * 4;                  // 0..508
    float4 s0 = make_float4(0.f, 0.f, 0.f, 0.f);
    float4 xv = make_float4(0.f, 0.f, 0.f, 0.f);
    if (row < N_NODES) {
        int start = g_ptr[row];
        int deg   = g_deg[row];
        float4 s1 = make_float4(0.f, 0.f, 0.f, 0.f);
        int i = 0;
        for (; i + 2 <= deg; i += 2) {
            int u0 = g_csr[start + i];
            int u1 = g_csr[start + i + 1];
            float4 a = __ldg((const float4*)(x + (size_t)u0 * DIM + c4));
            float4 b = __ldg((const float4*)(x + (size_t)u1 * DIM + c4));
            s0.x += a.x; s0.y += a.y; s0.z += a.z; s0.w += a.w;
            s1.x += b.x; s1.y += b.y; s1.z += b.z; s1.w += b.w;
        }
        if (i < deg) {
            int u0 = g_csr[start + i];
            float4 a = __ldg((const float4*)(x + (size_t)u0 * DIM + c4));
            s0.x += a.x; s0.y += a.y; s0.z += a.z; s0.w += a.w;
        }
        s0.x += s1.x; s0.y += s1.y; s0.z += s1.z; s0.w += s1.w;
        xv = __ldg((const float4*)(x + (size_t)row * DIM + c4));
    }
    split_store(s0, (size_t)row * KTOT + c4);          // agg half (cols 0..511)
    split_store(xv, (size_t)row * KTOT + 512 + c4);    // x half  (cols 512..1023)
}

// B[n][k]: n<512 -> [Wl1 | Wr1], n>=512 -> [Wl2 | Wr2]
__global__ void __launch_bounds__(256) convertB_kernel(
    const float* __restrict__ Wl1, const float* __restrict__ Wr1,
    const float* __restrict__ Wl2, const float* __restrict__ Wr2)
{
    int n  = blockIdx.x;                     // 0..1023
    int c4 = threadIdx.x * 4;
    const float* src = (n < 512) ? ((c4 < 512) ? Wl1 : Wr1)
                                 : ((c4 < 512) ? Wl2 : Wr2);
    float4 v = *(const float4*)(src + (size_t)(n & 511) * DIM + (c4 & 511));
    __nv_bfloat16 h0 = __float2bfloat16(v.x), h1 = __float2bfloat16(v.y);
    __nv_bfloat16 h2 = __float2bfloat16(v.z), h3 = __float2bfloat16(v.w);
    __nv_bfloat16 l0 = __float2bfloat16(v.x - __bfloat162float(h0));
    __nv_bfloat16 l1 = __float2bfloat16(v.y - __bfloat162float(h1));
    __nv_bfloat16 l2 = __float2bfloat16(v.z - __bfloat162float(h2));
    __nv_bfloat16 l3 = __float2bfloat16(v.w - __bfloat162float(h3));
    size_t o = (size_t)n * KTOT + c4;
    __nv_bfloat162 hA = {h0, h1}, hB = {h2, h3}, lA = {l0, l1}, lB = {l2, l3};
    *(uint2*)(g_Bhi + o) = make_uint2(*(uint32_t*)&hA, *(uint32_t*)&hB);
    *(uint2*)(g_Blo + o) = make_uint2(*(uint32_t*)&lA, *(uint32_t*)&lB);
}

// ---------------------------------------------------------------------------
// mma.sync GEMM: 128x128 CTA tile, BK=32, 3-stage cp.async pipeline.
// 8 warps, warp tile 64x32. D += Ahi*Bhi + Alo*Bhi + Ahi*Blo.
// ---------------------------------------------------------------------------
#define BK 32
#define AROW 80
#define TILE_SM (128 * AROW)            // 10240 B
#define BUF_SZ (4 * TILE_SM)            // 40960 B
#define NSTAGE 3
#define SMEM_DYN (NSTAGE * BUF_SZ)      // 122880 B
#define NK (KTOT / BK)                  // 32

__global__ void __launch_bounds__(256)
gemm_mma_kernel(const float* __restrict__ bl1, const float* __restrict__ bl2,
                float* __restrict__ out)
{
    extern __shared__ __align__(16) char dsmem[];
    __shared__ float bias_s[128];

    const int tid  = threadIdx.x;
    const int wid  = tid >> 5;
    const int lane = tid & 31;
    const int m0   = blockIdx.y * 128;
    const int n0   = blockIdx.x * 128;
    const bool isScale = (n0 >= 512);
    const int nLoc = n0 & 511;

    if (tid < 128) bias_s[tid] = (isScale ? bl2 : bl1)[nLoc + tid];

    const uint32_t sbase = smem_u32(dsmem);
    const __nv_bfloat16* srcs[4] = {
        g_Ahi + (size_t)m0 * KTOT, g_Alo + (size_t)m0 * KTOT,
        g_Bhi + (size_t)n0 * KTOT, g_Blo + (size_t)n0 * KTOT };

    auto load_stage = [&](int kt, int buf) {
        const int k0 = kt * BK;
        uint32_t bbase = sbase + buf * BUF_SZ;
#pragma unroll
        for (int i = 0; i < 8; ++i) {
            int t   = i >> 1;
            int idx = tid + ((i & 1) << 8);     // 0..511
            int row = idx >> 2;
            int c16 = idx & 3;
            const void* g = srcs[t] + (size_t)row * KTOT + k0 + c16 * 8;
            cp16(bbase + t * TILE_SM + row * AROW + c16 * 16, g);
        }
        cp_commit();
    };

    const int mw = (wid & 1) * 64;
    const int nw = (wid >> 1) * 32;

    float acc[4][4][4];
#pragma unroll
    for (int mt = 0; mt < 4; mt++)
#pragma unroll
        for (int nt = 0; nt < 4; nt++)
#pragma unroll
            for (int r = 0; r < 4; r++) acc[mt][nt][r] = 0.f;

    load_stage(0, 0);
    load_stage(1, 1);

    const int aRowOff = (lane & 15);
    const int aColB   = (lane >> 4) << 4;
    const int bRowOff = (lane & 7) + ((lane >> 4) << 3);
    const int bColB   = ((lane >> 3) & 1) << 4;

    int buf = 0;
    for (int kt = 0; kt < NK; ++kt) {
        cp_wait<1>();
        __syncthreads();

        const uint32_t bbase = sbase + buf * BUF_SZ;
#pragma unroll
        for (int ks = 0; ks < 2; ++ks) {
            const int kb = ks * 32;
            uint32_t ahi[4][4], alo[4][4], bhi[2][4], blo[2][4];
#pragma unroll
            for (int mt = 0; mt < 4; mt++) {
                uint32_t ra = bbase + (mw + mt * 16 + aRowOff) * AROW + kb + aColB;
                ldsm4(ahi[mt], ra);
                ldsm4(alo[mt], ra + TILE_SM);
            }
#pragma unroll
            for (int np = 0; np < 2; np++) {
                uint32_t rb = bbase + 2 * TILE_SM
                            + (nw + np * 16 + bRowOff) * AROW + kb + bColB;
                ldsm4(bhi[np], rb);
                ldsm4(blo[np], rb + TILE_SM);
            }
#pragma unroll
            for (int mt = 0; mt < 4; mt++)
#pragma unroll
                for (int nt = 0; nt < 4; nt++) {
                    const uint32_t* bh = &bhi[nt >> 1][(nt & 1) * 2];
                    const uint32_t* bl = &blo[nt >> 1][(nt & 1) * 2];
                    mma_bf16(acc[mt][nt], ahi[mt], bh);
                    mma_bf16(acc[mt][nt], alo[mt], bh);
                    mma_bf16(acc[mt][nt], ahi[mt], bl);
                }
        }
        if (kt + 2 < NK) {
            int nb = kt + 2;
            load_stage(nb, nb % NSTAGE);
        }
        buf = (buf + 1) % NSTAGE;
    }

    // ---- epilogue -----------------------------------------------------------
    const int rq = lane >> 2;
    const int cq = (lane & 3) * 2;
#pragma unroll
    for (int mt = 0; mt < 4; mt++) {
        int r0 = m0 + mw + mt * 16 + rq;
#pragma unroll
        for (int half = 0; half < 2; half++) {
            int m = r0 + half * 8;
            if (m >= N_NODES) continue;
            float* op = out + (isScale ? SCALE_OFF : 0) + (size_t)m * DIM + nLoc;
#pragma unroll
            for (int nt = 0; nt < 4; nt++) {
                int cl = nw + nt * 8 + cq;
                float v0 = acc[mt][nt][half * 2 + 0] + bias_s[cl];
                float v1 = acc[mt][nt][half * 2 + 1] + bias_s[cl + 1];
                if (!isScale) {
                    v0 = fminf(fmaxf(v0, -100.f), 100.f);
                    v1 = fminf(fmaxf(v1, -100.f), 100.f);
                } else {
                    v0 = fminf(fmaxf(v0, 0.f) + log1pf(expf(-fabsf(v0))) + 0.001f, 100.f);
                    v1 = fminf(fmaxf(v1, 0.f) + log1pf(expf(-fabsf(v1))) + 0.001f, 100.f);
                }
                *(float2*)(op + cl) = make_float2(v0, v1);
            }
        }
    }
}

// ---------------------------------------------------------------------------
extern "C" void kernel_launch(void* const* d_in, const int* in_sizes, int n_in,
                              void* d_out, int out_size)
{
    const float* x = 0;
    const void*  ei = 0;
    const float* Ws[4]; int nW = 0; int wpos[4];
    const float* bs[2]; int nb = 0; int bpos[2];
    for (int i = 0; i < n_in; i++) {
        int sz = in_sizes[i];
        if (sz == N_NODES * DIM)      x = (const float*)d_in[i];
        else if (sz == 2 * N_EDGES)   ei = d_in[i];
        else if (sz == DIM * DIM) { if (nW < 4) { wpos[nW] = i; Ws[nW++] = (const float*)d_in[i]; } }
        else if (sz == DIM)       { if (nb < 2) { bpos[nb] = i; bs[nb++] = (const float*)d_in[i]; } }
    }
    const float *Wl1, *Wr1, *Wl2, *Wr2, *bl1, *bl2;
    bl1 = bs[0]; bl2 = bs[1];
    if (nb == 2 && nW == 4 && bpos[0] < wpos[1]) {
        Wl1 = Ws[0]; Wr1 = Ws[1]; Wl2 = Ws[2]; Wr2 = Ws[3];   // dict order
    } else {
        Wl1 = Ws[0]; Wl2 = Ws[1]; Wr1 = Ws[2]; Wr2 = Ws[3];   // alphabetical
    }
    float* out = (float*)d_out;

    static int smem_set = 0;
    if (!smem_set) {
        cudaFuncSetAttribute(gemm_mma_kernel,
                             cudaFuncAttributeMaxDynamicSharedMemorySize, SMEM_DYN);
        smem_set = 1;
    }

    detect_idx_kernel<<<1, 32>>>(ei);
    zero_deg_kernel<<<49, 1024>>>();
    hist_kernel<<<3125, 256>>>(ei);
    scan1_kernel<<<NSCAN_BLK, 512>>>();
    scan2_kernel<<<1, 32>>>();
    scan3_kernel<<<NSCAN_BLK, 512>>>();
    fill_kernel<<<3125, 256>>>(ei);
    agg_convert_kernel<<<M_PAD, 128>>>(x);
    convertB_kernel<<<1024, 256>>>(Wl1, Wr1, Wl2, Wr2);
    gemm_mma_kernel<<<dim3(8, 391), 256, SMEM_DYN>>>(bl1, bl2, out);
}

// round 12
// speedup vs baseline: 3.4801x; 1.4987x over previous
#include <cuda_runtime.h>
#include <cuda_fp16.h>
#include <math.h>
#include <stdint.h>

#define N_NODES 50000
#define N_EDGES 800000
#define DIM 512
#define KTOT 1024
#define SCALE_OFF ((size_t)N_NODES * DIM)
#define M_PAD 50048                      // 391 * 128
#define NSCAN_BLK 98                     // ceil(50000/512)

// ---------------- scratch (__device__ globals) ------------------------------
__device__ __half g_A[(size_t)M_PAD * KTOT];                   // 102 MB
__device__ __half g_B[(size_t)KTOT * KTOT];                    // 2 MB
__device__ int g_deg[N_NODES];
__device__ int g_ptr[N_NODES];
__device__ int g_cursor[N_NODES];
__device__ int g_bsum[NSCAN_BLK];
__device__ int g_boff[NSCAN_BLK];
__device__ int g_csr[N_EDGES];
__device__ int g_idx64;

// ---------------- PTX helpers (sm_80-level only; no 'a' features) -----------
__device__ __forceinline__ uint32_t smem_u32(const void* p) {
    uint32_t a;
    asm("{ .reg .u64 t; cvta.to.shared.u64 t, %1; cvt.u32.u64 %0, t; }" : "=r"(a) : "l"(p));
    return a;
}
__device__ __forceinline__ void cp16(uint32_t saddr, const void* g) {
    asm volatile("cp.async.cg.shared.global [%0], [%1], 16;" :: "r"(saddr), "l"(g));
}
__device__ __forceinline__ void cp_commit() {
    asm volatile("cp.async.commit_group;" ::: "memory");
}
template <int N>
__device__ __forceinline__ void cp_wait() {
    asm volatile("cp.async.wait_group %0;" :: "n"(N) : "memory");
}
__device__ __forceinline__ void ldsm4(uint32_t* r, uint32_t addr) {
    asm volatile("ldmatrix.sync.aligned.m8n8.x4.shared.b16 {%0,%1,%2,%3}, [%4];"
        : "=r"(r[0]), "=r"(r[1]), "=r"(r[2]), "=r"(r[3]) : "r"(addr));
}
__device__ __forceinline__ void mma_f16(float* c, const uint32_t* a, const uint32_t* b) {
    asm volatile("mma.sync.aligned.m16n8k16.row.col.f32.f16.f16.f32 "
        "{%0,%1,%2,%3}, {%4,%5,%6,%7}, {%8,%9}, {%0,%1,%2,%3};"
        : "+f"(c[0]), "+f"(c[1]), "+f"(c[2]), "+f"(c[3])
        : "r"(a[0]), "r"(a[1]), "r"(a[2]), "r"(a[3]), "r"(b[0]), "r"(b[1]));
}

// ---------------------------------------------------------------------------
__global__ void detect_idx_kernel(const void* __restrict__ ei) {
    if (threadIdx.x == 0 && blockIdx.x == 0) {
        const long long* p = (const long long*)ei;
        int is64 = 1;
        for (int i = 0; i < 64; i++) {
            long long v = p[i];
            if (v < 0 || v >= N_NODES) { is64 = 0; break; }
        }
        g_idx64 = is64;
    }
}

__global__ void __launch_bounds__(1024) zero_deg_kernel() {
    int i = blockIdx.x * 1024 + threadIdx.x;
    if (i < N_NODES) g_deg[i] = 0;
}

__global__ void __launch_bounds__(256) hist_kernel(const void* __restrict__ ei) {
    int e = blockIdx.x * blockDim.x + threadIdx.x;
    if (e >= N_EDGES) return;
    int d = g_idx64 ? (int)((const long long*)ei)[N_EDGES + e]
                    : ((const int*)ei)[N_EDGES + e];
    if ((unsigned)d < N_NODES) atomicAdd(&g_deg[d], 1);
}

// Block-wise exclusive scan of g_deg (512/block); block sums to g_bsum.
__global__ void __launch_bounds__(512) scan1_kernel() {
    __shared__ int sm[512];
    int b = blockIdx.x, t = threadIdx.x;
    int i = b * 512 + t;
    int v = (i < N_NODES) ? g_deg[i] : 0;
    sm[t] = v;
    __syncthreads();
#pragma unroll
    for (int off = 1; off < 512; off <<= 1) {
        int u = (t >= off) ? sm[t - off] : 0;
        __syncthreads();
        sm[t] += u;
        __syncthreads();
    }
    if (i < N_NODES) g_ptr[i] = sm[t] - v;        // exclusive within block
    if (t == 511) g_bsum[b] = sm[511];
}

__global__ void scan2_kernel() {
    if (threadIdx.x == 0 && blockIdx.x == 0) {
        int run = 0;
        for (int b = 0; b < NSCAN_BLK; b++) { g_boff[b] = run; run += g_bsum[b]; }
    }
}

__global__ void __launch_bounds__(512) scan3_kernel() {
    int i = blockIdx.x * 512 + threadIdx.x;
    if (i < N_NODES) {
        int v = g_ptr[i] + g_boff[i >> 9];
        g_ptr[i] = v;
        g_cursor[i] = v;
    }
}

__global__ void __launch_bounds__(256) fill_kernel(const void* __restrict__ ei) {
    int e = blockIdx.x * blockDim.x + threadIdx.x;
    if (e >= N_EDGES) return;
    int s, d;
    if (g_idx64) {
        const long long* p = (const long long*)ei;
        s = (int)p[e]; d = (int)p[N_EDGES + e];
    } else {
        const int* p = (const int*)ei;
        s = p[e]; d = p[N_EDGES + e];
    }
    if ((unsigned)s >= N_NODES || (unsigned)d >= N_NODES) return;
    int pos = atomicAdd(&g_cursor[d], 1);
    g_csr[pos] = s;
}

// ---------------------------------------------------------------------------
// Aggregate (CSR, register accumulation) + fused fp16 convert of A = [agg | x].
// One block (128 thr) per padded row; thread owns 4 floats of each half.
// ---------------------------------------------------------------------------
__device__ __forceinline__ void h_store(float4 v, size_t o) {
    __half2 a = __floats2half2_rn(v.x, v.y);
    __half2 b = __floats2half2_rn(v.z, v.w);
    *(uint2*)(g_A + o) = make_uint2(*(uint32_t*)&a, *(uint32_t*)&b);
}

__global__ void __launch_bounds__(128) agg_convert_kernel(const float* __restrict__ x) {
    int row = blockIdx.x;                       // 0..M_PAD-1
    int c4  = threadIdx.x * 4;                  // 0..508
    float4 s0 = make_float4(0.f, 0.f, 0.f, 0.f);
    float4 xv = make_float4(0.f, 0.f, 0.f, 0.f);
    if (row < N_NODES) {
        int start = g_ptr[row];
        int deg   = g_deg[row];
        float4 s1 = make_float4(0.f, 0.f, 0.f, 0.f);
        int i = 0;
        for (; i + 2 <= deg; i += 2) {
            int u0 = g_csr[start + i];
            int u1 = g_csr[start + i + 1];
            float4 a = __ldg((const float4*)(x + (size_t)u0 * DIM + c4));
            float4 b = __ldg((const float4*)(x + (size_t)u1 * DIM + c4));
            s0.x += a.x; s0.y += a.y; s0.z += a.z; s0.w += a.w;
            s1.x += b.x; s1.y += b.y; s1.z += b.z; s1.w += b.w;
        }
        if (i < deg) {
            int u0 = g_csr[start + i];
            float4 a = __ldg((const float4*)(x + (size_t)u0 * DIM + c4));
            s0.x += a.x; s0.y += a.y; s0.z += a.z; s0.w += a.w;
        }
        s0.x += s1.x; s0.y += s1.y; s0.z += s1.z; s0.w += s1.w;
        xv = __ldg((const float4*)(x + (size_t)row * DIM + c4));
    }
    h_store(s0, (size_t)row * KTOT + c4);          // agg half (cols 0..511)
    h_store(xv, (size_t)row * KTOT + 512 + c4);    // x half  (cols 512..1023)
}

// B[n][k]: n<512 -> [Wl1 | Wr1], n>=512 -> [Wl2 | Wr2]
__global__ void __launch_bounds__(256) convertB_kernel(
    const float* __restrict__ Wl1, const float* __restrict__ Wr1,
    const float* __restrict__ Wl2, const float* __restrict__ Wr2)
{
    int n  = blockIdx.x;                     // 0..1023
    int c4 = threadIdx.x * 4;
    const float* src = (n < 512) ? ((c4 < 512) ? Wl1 : Wr1)
                                 : ((c4 < 512) ? Wl2 : Wr2);
    float4 v = *(const float4*)(src + (size_t)(n & 511) * DIM + (c4 & 511));
    __half2 a = __floats2half2_rn(v.x, v.y);
    __half2 b = __floats2half2_rn(v.z, v.w);
    *(uint2*)(g_B + (size_t)n * KTOT + c4) = make_uint2(*(uint32_t*)&a, *(uint32_t*)&b);
}

// ---------------------------------------------------------------------------
// Single-pass fp16 mma.sync GEMM: 128x128 CTA tile, BK=32, 4-stage cp.async.
// 8 warps, warp tile 64x32 (m16n8k16 x 4m x 4n x 2k).
// ---------------------------------------------------------------------------
#define BK 32
#define AROW 80
#define TILE_SM (128 * AROW)            // 10240 B
#define BUF_SZ (2 * TILE_SM)            // 20480 B (A tile + B tile)
#define NSTAGE 4
#define SMEM_DYN (NSTAGE * BUF_SZ)      // 81920 B
#define NK (KTOT / BK)                  // 32

__global__ void __launch_bounds__(256)
gemm_mma_kernel(const float* __restrict__ bl1, const float* __restrict__ bl2,
                float* __restrict__ out)
{
    extern __shared__ __align__(16) char dsmem[];
    __shared__ float bias_s[128];

    const int tid  = threadIdx.x;
    const int wid  = tid >> 5;
    const int lane = tid & 31;
    const int m0   = blockIdx.y * 128;
    const int n0   = blockIdx.x * 128;
    const bool isScale = (n0 >= 512);
    const int nLoc = n0 & 511;

    if (tid < 128) bias_s[tid] = (isScale ? bl2 : bl1)[nLoc + tid];

    const uint32_t sbase = smem_u32(dsmem);
    const __half* srcs[2] = { g_A + (size_t)m0 * KTOT, g_B + (size_t)n0 * KTOT };

    // stage loader: 2 tiles x 128 rows x 64B = 1024 x 16B chunks, 4/thread
    auto load_stage = [&](int kt, int buf) {
        const int k0 = kt * BK;
        uint32_t bbase = sbase + buf * BUF_SZ;
#pragma unroll
        for (int i = 0; i < 4; ++i) {
            int id  = tid + (i << 8);           // 0..1023
            int t   = id >> 9;                  // 0=A, 1=B
            int loc = id & 511;
            int row = loc >> 2;
            int c16 = loc & 3;
            const void* g = srcs[t] + (size_t)row * KTOT + k0 + c16 * 8;
            cp16(bbase + t * TILE_SM + row * AROW + c16 * 16, g);
        }
        cp_commit();
    };

    const int mw = (wid & 1) * 64;
    const int nw = (wid >> 1) * 32;

    float acc[4][4][4];
#pragma unroll
    for (int mt = 0; mt < 4; mt++)
#pragma unroll
        for (int nt = 0; nt < 4; nt++)
#pragma unroll
            for (int r = 0; r < 4; r++) acc[mt][nt][r] = 0.f;

    load_stage(0, 0);
    load_stage(1, 1);
    load_stage(2, 2);

    const int aRowOff = (lane & 15);
    const int aColB   = (lane >> 4) << 4;
    const int bRowOff = (lane & 7) + ((lane >> 4) << 3);
    const int bColB   = ((lane >> 3) & 1) << 4;

    int buf = 0;
    for (int kt = 0; kt < NK; ++kt) {
        cp_wait<2>();
        __syncthreads();

        const uint32_t bbase = sbase + buf * BUF_SZ;
#pragma unroll
        for (int ks = 0; ks < 2; ++ks) {
            const int kb = ks * 32;
            uint32_t af[4][4], bf[2][4];
#pragma unroll
            for (int mt = 0; mt < 4; mt++)
                ldsm4(af[mt], bbase + (mw + mt * 16 + aRowOff) * AROW + kb + aColB);
#pragma unroll
            for (int np = 0; np < 2; np++)
                ldsm4(bf[np], bbase + TILE_SM
                              + (nw + np * 16 + bRowOff) * AROW + kb + bColB);
#pragma unroll
            for (int mt = 0; mt < 4; mt++)
#pragma unroll
                for (int nt = 0; nt < 4; nt++)
                    mma_f16(acc[mt][nt], af[mt], &bf[nt >> 1][(nt & 1) * 2]);
        }
        if (kt + 3 < NK) load_stage(kt + 3, (kt + 3) % NSTAGE);
        buf = (buf + 1) % NSTAGE;
    }

    // ---- epilogue -----------------------------------------------------------
    const int rq = lane >> 2;
    const int cq = (lane & 3) * 2;
#pragma unroll
    for (int mt = 0; mt < 4; mt++) {
        int r0 = m0 + mw + mt * 16 + rq;
#pragma unroll
        for (int half = 0; half < 2; half++) {
            int m = r0 + half * 8;
            if (m >= N_NODES) continue;
            float* op = out + (isScale ? SCALE_OFF : 0) + (size_t)m * DIM + nLoc;
#pragma unroll
            for (int nt = 0; nt < 4; nt++) {
                int cl = nw + nt * 8 + cq;
                float v0 = acc[mt][nt][half * 2 + 0] + bias_s[cl];
                float v1 = acc[mt][nt][half * 2 + 1] + bias_s[cl + 1];
                if (!isScale) {
                    v0 = fminf(fmaxf(v0, -100.f), 100.f);
                    v1 = fminf(fmaxf(v1, -100.f), 100.f);
                } else {
                    v0 = fminf(fmaxf(v0, 0.f) + log1pf(expf(-fabsf(v0))) + 0.001f, 100.f);
                    v1 = fminf(fmaxf(v1, 0.f) + log1pf(expf(-fabsf(v1))) + 0.001f, 100.f);
                }
                *(float2*)(op + cl) = make_float2(v0, v1);
            }
        }
    }
}

// ---------------------------------------------------------------------------
extern "C" void kernel_launch(void* const* d_in, const int* in_sizes, int n_in,
                              void* d_out, int out_size)
{
    const float* x = 0;
    const void*  ei = 0;
    const float* Ws[4]; int nW = 0; int wpos[4];
    const float* bs[2]; int nb = 0; int bpos[2];
    for (int i = 0; i < n_in; i++) {
        int sz = in_sizes[i];
        if (sz == N_NODES * DIM)      x = (const float*)d_in[i];
        else if (sz == 2 * N_EDGES)   ei = d_in[i];
        else if (sz == DIM * DIM) { if (nW < 4) { wpos[nW] = i; Ws[nW++] = (const float*)d_in[i]; } }
        else if (sz == DIM)       { if (nb < 2) { bpos[nb] = i; bs[nb++] = (const float*)d_in[i]; } }
    }
    const float *Wl1, *Wr1, *Wl2, *Wr2, *bl1, *bl2;
    bl1 = bs[0]; bl2 = bs[1];
    if (nb == 2 && nW == 4 && bpos[0] < wpos[1]) {
        Wl1 = Ws[0]; Wr1 = Ws[1]; Wl2 = Ws[2]; Wr2 = Ws[3];   // dict order
    } else {
        Wl1 = Ws[0]; Wl2 = Ws[1]; Wr1 = Ws[2]; Wr2 = Ws[3];   // alphabetical
    }
    float* out = (float*)d_out;

    static int smem_set = 0;
    if (!smem_set) {
        cudaFuncSetAttribute(gemm_mma_kernel,
                             cudaFuncAttributeMaxDynamicSharedMemorySize, SMEM_DYN);
        smem_set = 1;
    }

    detect_idx_kernel<<<1, 32>>>(ei);
    zero_deg_kernel<<<49, 1024>>>();
    hist_kernel<<<3125, 256>>>(ei);
    scan1_kernel<<<NSCAN_BLK, 512>>>();
    scan2_kernel<<<1, 32>>>();
    scan3_kernel<<<NSCAN_BLK, 512>>>();
    fill_kernel<<<3125, 256>>>(ei);
    agg_convert_kernel<<<M_PAD, 128>>>(x);
    convertB_kernel<<<1024, 256>>>(Wl1, Wr1, Wl2, Wr2);
    gemm_mma_kernel<<<dim3(8, 391), 256, SMEM_DYN>>>(bl1, bl2, out);
}

// round 14
// speedup vs baseline: 4.8500x; 1.3937x over previous
#include <cuda_runtime.h>
#include <cuda_fp16.h>
#include <math.h>
#include <stdint.h>

#define N_NODES 50000
#define N_EDGES 800000
#define DIM 512
#define KTOT 1024
#define SCALE_OFF ((size_t)N_NODES * DIM)
#define M_PAD 50048                      // 391 * 128
#define NSCAN_BLK 98                     // ceil(50000/512)

// ---------------- scratch (__device__ globals) ------------------------------
__device__ __half g_A[(size_t)M_PAD * KTOT];                   // 102 MB
__device__ __half g_B[(size_t)KTOT * KTOT];                    // 2 MB
__device__ int g_deg[N_NODES];
__device__ int g_ptr[N_NODES];
__device__ int g_cursor[N_NODES];
__device__ int g_bsum[NSCAN_BLK];
__device__ int g_boff[NSCAN_BLK];
__device__ int g_csr[N_EDGES];
__device__ int g_idx64;

// ---------------- PTX helpers (sm_80-level only; no 'a' features) -----------
__device__ __forceinline__ uint32_t smem_u32(const void* p) {
    uint32_t a;
    asm("{ .reg .u64 t; cvta.to.shared.u64 t, %1; cvt.u32.u64 %0, t; }" : "=r"(a) : "l"(p));
    return a;
}
__device__ __forceinline__ void cp16(uint32_t saddr, const void* g) {
    asm volatile("cp.async.cg.shared.global [%0], [%1], 16;" :: "r"(saddr), "l"(g));
}
__device__ __forceinline__ void cp_commit() {
    asm volatile("cp.async.commit_group;" ::: "memory");
}
template <int N>
__device__ __forceinline__ void cp_wait() {
    asm volatile("cp.async.wait_group %0;" :: "n"(N) : "memory");
}
__device__ __forceinline__ void ldsm4(uint32_t* r, uint32_t addr) {
    asm volatile("ldmatrix.sync.aligned.m8n8.x4.shared.b16 {%0,%1,%2,%3}, [%4];"
        : "=r"(r[0]), "=r"(r[1]), "=r"(r[2]), "=r"(r[3]) : "r"(addr));
}
__device__ __forceinline__ void mma_f16(float* c, const uint32_t* a, const uint32_t* b) {
    asm volatile("mma.sync.aligned.m16n8k16.row.col.f32.f16.f16.f32 "
        "{%0,%1,%2,%3}, {%4,%5,%6,%7}, {%8,%9}, {%0,%1,%2,%3};"
        : "+f"(c[0]), "+f"(c[1]), "+f"(c[2]), "+f"(c[3])
        : "r"(a[0]), "r"(a[1]), "r"(a[2]), "r"(a[3]), "r"(b[0]), "r"(b[1]));
}

// ---------------------------------------------------------------------------
__global__ void detect_idx_kernel(const void* __restrict__ ei) {
    if (threadIdx.x == 0 && blockIdx.x == 0) {
        const long long* p = (const long long*)ei;
        int is64 = 1;
        for (int i = 0; i < 64; i++) {
            long long v = p[i];
            if (v < 0 || v >= N_NODES) { is64 = 0; break; }
        }
        g_idx64 = is64;
    }
}

__global__ void __launch_bounds__(1024) zero_deg_kernel() {
    int i = blockIdx.x * 1024 + threadIdx.x;
    if (i < N_NODES) g_deg[i] = 0;
}

__global__ void __launch_bounds__(256) hist_kernel(const void* __restrict__ ei) {
    int e = blockIdx.x * blockDim.x + threadIdx.x;
    if (e >= N_EDGES) return;
    int d = g_idx64 ? (int)((const long long*)ei)[N_EDGES + e]
                    : ((const int*)ei)[N_EDGES + e];
    if ((unsigned)d < N_NODES) atomicAdd(&g_deg[d], 1);
}

// Block-wise exclusive scan of g_deg (512/block); block sums to g_bsum.
__global__ void __launch_bounds__(512) scan1_kernel() {
    __shared__ int sm[512];
    int b = blockIdx.x, t = threadIdx.x;
    int i = b * 512 + t;
    int v = (i < N_NODES) ? g_deg[i] : 0;
    sm[t] = v;
    __syncthreads();
#pragma unroll
    for (int off = 1; off < 512; off <<= 1) {
        int u = (t >= off) ? sm[t - off] : 0;
        __syncthreads();
        sm[t] += u;
        __syncthreads();
    }
    if (i < N_NODES) g_ptr[i] = sm[t] - v;        // exclusive within block
    if (t == 511) g_bsum[b] = sm[511];
}

__global__ void scan2_kernel() {
    if (threadIdx.x == 0 && blockIdx.x == 0) {
        int run = 0;
        for (int b = 0; b < NSCAN_BLK; b++) { g_boff[b] = run; run += g_bsum[b]; }
    }
}

__global__ void __launch_bounds__(512) scan3_kernel() {
    int i = blockIdx.x * 512 + threadIdx.x;
    if (i < N_NODES) {
        int v = g_ptr[i] + g_boff[i >> 9];
        g_ptr[i] = v;
        g_cursor[i] = v;
    }
}

__global__ void __launch_bounds__(256) fill_kernel(const void* __restrict__ ei) {
    int e = blockIdx.x * blockDim.x + threadIdx.x;
    if (e >= N_EDGES) return;
    int s, d;
    if (g_idx64) {
        const long long* p = (const long long*)ei;
        s = (int)p[e]; d = (int)p[N_EDGES + e];
    } else {
        const int* p = (const int*)ei;
        s = p[e]; d = p[N_EDGES + e];
    }
    if ((unsigned)s >= N_NODES || (unsigned)d >= N_NODES) return;
    int pos = atomicAdd(&g_cursor[d], 1);
    g_csr[pos] = s;
}

// ---------------------------------------------------------------------------
// Stage 1: x -> fp16 into the x-half of A (cols 512..1023). Pads zeroed.
// ---------------------------------------------------------------------------
__global__ void __launch_bounds__(128) convertX_kernel(const float* __restrict__ x) {
    int row = blockIdx.x;                        // 0..M_PAD-1
    int c4  = threadIdx.x * 4;                   // 0..508
    float4 v = make_float4(0.f, 0.f, 0.f, 0.f);
    if (row < N_NODES)
        v = __ldg((const float4*)(x + (size_t)row * DIM + c4));
    __half2 a = __floats2half2_rn(v.x, v.y);
    __half2 b = __floats2half2_rn(v.z, v.w);
    *(uint2*)(g_A + (size_t)row * KTOT + 512 + c4) = make_uint2(*(uint32_t*)&a, *(uint32_t*)&b);
}

// ---------------------------------------------------------------------------
// Stage 2: CSR aggregate, gathering fp16 x-rows (L2-resident), fp32 accum,
// write fp16 agg into cols 0..511. 64 threads/row, 8 cols each (16B loads).
// ---------------------------------------------------------------------------
__global__ void __launch_bounds__(64) agg_convert_kernel() {
    int row = blockIdx.x;                        // 0..M_PAD-1
    int c8  = threadIdx.x * 8;                   // 0..504
    float s[8];
#pragma unroll
    for (int j = 0; j < 8; j++) s[j] = 0.f;
    if (row < N_NODES) {
        int start = g_ptr[row];
        int deg   = g_deg[row];
        for (int i = 0; i < deg; i++) {
            int u = g_csr[start + i];
            uint4 h = __ldg((const uint4*)(g_A + (size_t)u * KTOT + 512 + c8));
            const __half2* hp = (const __half2*)&h;
#pragma unroll
            for (int p = 0; p < 4; p++) {
                float2 f = __half22float2(hp[p]);
                s[2 * p]     += f.x;
                s[2 * p + 1] += f.y;
            }
        }
    }
    __half2 o0 = __floats2half2_rn(s[0], s[1]);
    __half2 o1 = __floats2half2_rn(s[2], s[3]);
    __half2 o2 = __floats2half2_rn(s[4], s[5]);
    __half2 o3 = __floats2half2_rn(s[6], s[7]);
    uint4 ov = make_uint4(*(uint32_t*)&o0, *(uint32_t*)&o1, *(uint32_t*)&o2, *(uint32_t*)&o3);
    *(uint4*)(g_A + (size_t)row * KTOT + c8) = ov;
}

// B[n][k]: n<512 -> [Wl1 | Wr1], n>=512 -> [Wl2 | Wr2]
__global__ void __launch_bounds__(256) convertB_kernel(
    const float* __restrict__ Wl1, const float* __restrict__ Wr1,
    const float* __restrict__ Wl2, const float* __restrict__ Wr2)
{
    int n  = blockIdx.x;                     // 0..1023
    int c4 = threadIdx.x * 4;
    const float* src = (n < 512) ? ((c4 < 512) ? Wl1 : Wr1)
                                 : ((c4 < 512) ? Wl2 : Wr2);
    float4 v = *(const float4*)(src + (size_t)(n & 511) * DIM + (c4 & 511));
    __half2 a = __floats2half2_rn(v.x, v.y);
    __half2 b = __floats2half2_rn(v.z, v.w);
    *(uint2*)(g_B + (size_t)n * KTOT + c4) = make_uint2(*(uint32_t*)&a, *(uint32_t*)&b);
}

// ---------------------------------------------------------------------------
// fp16 mma.sync GEMM: 128x256 CTA tile, BK=32, 4-stage cp.async.
// 8 warps (2M x 4N), warp tile 64x64 (m16n8k16 x 4m x 8n x 2k).
// ---------------------------------------------------------------------------
#define BK 32
#define AROW 80
#define A_SM (128 * AROW)               // 10240 B
#define B_SM (256 * AROW)               // 20480 B
#define BUF_SZ (A_SM + B_SM)            // 30720 B
#define NSTAGE 4
#define SMEM_DYN (NSTAGE * BUF_SZ)      // 122880 B
#define NK (KTOT / BK)                  // 32

__global__ void __launch_bounds__(256, 1)
gemm_mma_kernel(const float* __restrict__ bl1, const float* __restrict__ bl2,
                float* __restrict__ out)
{
    extern __shared__ __align__(16) char dsmem[];
    __shared__ float bias_s[256];

    const int tid  = threadIdx.x;
    const int wid  = tid >> 5;
    const int lane = tid & 31;
    const int m0   = blockIdx.y * 128;
    const int n0   = blockIdx.x * 256;      // 0,256,512,768
    const bool isScale = (n0 >= 512);
    const int nLoc = n0 & 511;              // 0 or 256

    if (tid < 256) bias_s[tid] = (isScale ? bl2 : bl1)[nLoc + tid];

    const uint32_t sbase = smem_u32(dsmem);
    const __half* srcA = g_A + (size_t)m0 * KTOT;
    const __half* srcB = g_B + (size_t)n0 * KTOT;

    // stage loader: A 512 chunks + B 1024 chunks of 16B; 6 per thread
    auto load_stage = [&](int kt, int buf) {
        const int k0 = kt * BK;
        uint32_t bbase = sbase + buf * BUF_SZ;
#pragma unroll
        for (int i = 0; i < 6; ++i) {
            int id = tid + (i << 8);            // 0..1535
            if (id < 512) {
                int row = id >> 2, c16 = id & 3;
                cp16(bbase + row * AROW + c16 * 16,
                     srcA + (size_t)row * KTOT + k0 + c16 * 8);
            } else {
                int loc = id - 512;
                int row = loc >> 2, c16 = loc & 3;
                cp16(bbase + A_SM + row * AROW + c16 * 16,
                     srcB + (size_t)row * KTOT + k0 + c16 * 8);
            }
        }
        cp_commit();
    };

    const int mw = (wid & 1) * 64;          // warp M offset
    const int nw = (wid >> 1) * 64;         // warp N offset

    float acc[4][8][4];
#pragma unroll
    for (int mt = 0; mt < 4; mt++)
#pragma unroll
        for (int nt = 0; nt < 8; nt++)
#pragma unroll
            for (int r = 0; r < 4; r++) acc[mt][nt][r] = 0.f;

    load_stage(0, 0);
    load_stage(1, 1);
    load_stage(2, 2);

    const int aRowOff = (lane & 15);
    const int aColB   = (lane >> 4) << 4;
    const int bRowOff = (lane & 7) + ((lane >> 4) << 3);
    const int bColB   = ((lane >> 3) & 1) << 4;

    int buf = 0;
    for (int kt = 0; kt < NK; ++kt) {
        cp_wait<2>();
        __syncthreads();

        const uint32_t bbase = sbase + buf * BUF_SZ;
#pragma unroll
        for (int ks = 0; ks < 2; ++ks) {
            const int kb = ks * 32;
            uint32_t af[4][4], bf[4][4];
#pragma unroll
            for (int mt = 0; mt < 4; mt++)
                ldsm4(af[mt], bbase + (mw + mt * 16 + aRowOff) * AROW + kb + aColB);
#pragma unroll
            for (int np = 0; np < 4; np++)
                ldsm4(bf[np], bbase + A_SM
                              + (nw + np * 16 + bRowOff) * AROW + kb + bColB);
#pragma unroll
            for (int mt = 0; mt < 4; mt++)
#pragma unroll
                for (int nt = 0; nt < 8; nt++)
                    mma_f16(acc[mt][nt], af[mt], &bf[nt >> 1][(nt & 1) * 2]);
        }
        if (kt + 3 < NK) load_stage(kt + 3, (kt + 3) % NSTAGE);
        buf = (buf + 1) % NSTAGE;
    }

    // ---- epilogue -----------------------------------------------------------
    const int rq = lane >> 2;
    const int cq = (lane & 3) * 2;
#pragma unroll
    for (int mt = 0; mt < 4; mt++) {
        int r0 = m0 + mw + mt * 16 + rq;
#pragma unroll
        for (int half = 0; half < 2; half++) {
            int m = r0 + half * 8;
            if (m >= N_NODES) continue;
            float* op = out + (isScale ? SCALE_OFF : 0) + (size_t)m * DIM + nLoc;
#pragma unroll
            for (int nt = 0; nt < 8; nt++) {
                int cl = nw + nt * 8 + cq;
                float v0 = acc[mt][nt][half * 2 + 0] + bias_s[cl];
                float v1 = acc[mt][nt][half * 2 + 1] + bias_s[cl + 1];
                if (!isScale) {
                    v0 = fminf(fmaxf(v0, -100.f), 100.f);
                    v1 = fminf(fmaxf(v1, -100.f), 100.f);
                } else {
                    v0 = fminf(fmaxf(v0, 0.f) + log1pf(expf(-fabsf(v0))) + 0.001f, 100.f);
                    v1 = fminf(fmaxf(v1, 0.f) + log1pf(expf(-fabsf(v1))) + 0.001f, 100.f);
                }
                *(float2*)(op + cl) = make_float2(v0, v1);
            }
        }
    }
}

// ---------------------------------------------------------------------------
extern "C" void kernel_launch(void* const* d_in, const int* in_sizes, int n_in,
                              void* d_out, int out_size)
{
    const float* x = 0;
    const void*  ei = 0;
    const float* Ws[4]; int nW = 0; int wpos[4];
    const float* bs[2]; int nb = 0; int bpos[2];
    for (int i = 0; i < n_in; i++) {
        int sz = in_sizes[i];
        if (sz == N_NODES * DIM)      x = (const float*)d_in[i];
        else if (sz == 2 * N_EDGES)   ei = d_in[i];
        else if (sz == DIM * DIM) { if (nW < 4) { wpos[nW] = i; Ws[nW++] = (const float*)d_in[i]; } }
        else if (sz == DIM)       { if (nb < 2) { bpos[nb] = i; bs[nb++] = (const float*)d_in[i]; } }
    }
    const float *Wl1, *Wr1, *Wl2, *Wr2, *bl1, *bl2;
    bl1 = bs[0]; bl2 = bs[1];
    if (nb == 2 && nW == 4 && bpos[0] < wpos[1]) {
        Wl1 = Ws[0]; Wr1 = Ws[1]; Wl2 = Ws[2]; Wr2 = Ws[3];   // dict order
    } else {
        Wl1 = Ws[0]; Wl2 = Ws[1]; Wr1 = Ws[2]; Wr2 = Ws[3];   // alphabetical
    }
    float* out = (float*)d_out;

    static int smem_set = 0;
    if (!smem_set) {
        cudaFuncSetAttribute(gemm_mma_kernel,
                             cudaFuncAttributeMaxDynamicSharedMemorySize, SMEM_DYN);
        smem_set = 1;
    }

    detect_idx_kernel<<<1, 32>>>(ei);
    zero_deg_kernel<<<49, 1024>>>();
    hist_kernel<<<3125, 256>>>(ei);
    scan1_kernel<<<NSCAN_BLK, 512>>>();
    scan2_kernel<<<1, 32>>>();
    scan3_kernel<<<NSCAN_BLK, 512>>>();
    fill_kernel<<<3125, 256>>>(ei);
    convertX_kernel<<<M_PAD, 128>>>(x);
    agg_convert_kernel<<<M_PAD, 64>>>();
    convertB_kernel<<<1024, 256>>>(Wl1, Wr1, Wl2, Wr2);
    gemm_mma_kernel<<<dim3(4, 391), 256, SMEM_DYN>>>(bl1, bl2, out);
}

// round 17
// speedup vs baseline: 4.8794x; 1.0061x over previous
#include <cuda_runtime.h>
#include <cuda_fp16.h>
#include <math.h>
#include <stdint.h>

#define N_NODES 50000
#define N_EDGES 800000
#define DIM 512
#define KTOT 1024
#define SCALE_OFF ((size_t)N_NODES * DIM)
#define M_PAD 50048                      // 391 * 128
#define NSCAN_BLK 98                     // ceil(50000/512)

// ---------------- scratch (__device__ globals) ------------------------------
__device__ __half g_A[(size_t)M_PAD * KTOT];                   // 102 MB
__device__ __half g_B[(size_t)KTOT * KTOT];                    // 2 MB
__device__ int g_deg[N_NODES];
__device__ int g_ptr[N_NODES];
__device__ int g_cursor[N_NODES];
__device__ int g_bsum[NSCAN_BLK];
__device__ int g_boff[NSCAN_BLK];
__device__ int g_csr[N_EDGES];
__device__ int g_idx64;

// ---------------- PTX helpers (sm_80-level only; no 'a' features) -----------
__device__ __forceinline__ uint32_t smem_u32(const void* p) {
    uint32_t a;
    asm("{ .reg .u64 t; cvta.to.shared.u64 t, %1; cvt.u32.u64 %0, t; }" : "=r"(a) : "l"(p));
    return a;
}
__device__ __forceinline__ void cp16(uint32_t saddr, const void* g) {
    asm volatile("cp.async.cg.shared.global [%0], [%1], 16;" :: "r"(saddr), "l"(g));
}
__device__ __forceinline__ void cp_commit() {
    asm volatile("cp.async.commit_group;" ::: "memory");
}
template <int N>
__device__ __forceinline__ void cp_wait() {
    asm volatile("cp.async.wait_group %0;" :: "n"(N) : "memory");
}
__device__ __forceinline__ void ldsm4(uint32_t* r, uint32_t addr) {
    asm volatile("ldmatrix.sync.aligned.m8n8.x4.shared.b16 {%0,%1,%2,%3}, [%4];"
        : "=r"(r[0]), "=r"(r[1]), "=r"(r[2]), "=r"(r[3]) : "r"(addr));
}
__device__ __forceinline__ void mma_f16(float* c, const uint32_t* a, const uint32_t* b) {
    asm volatile("mma.sync.aligned.m16n8k16.row.col.f32.f16.f16.f32 "
        "{%0,%1,%2,%3}, {%4,%5,%6,%7}, {%8,%9}, {%0,%1,%2,%3};"
        : "+f"(c[0]), "+f"(c[1]), "+f"(c[2]), "+f"(c[3])
        : "r"(a[0]), "r"(a[1]), "r"(a[2]), "r"(a[3]), "r"(b[0]), "r"(b[1]));
}

// ---------------------------------------------------------------------------
// zero g_deg; block 0 thread 0 also detects edge_index dtype.
__global__ void __launch_bounds__(1024) zero_detect_kernel(const void* __restrict__ ei) {
    int i = blockIdx.x * 1024 + threadIdx.x;
    if (i < N_NODES) g_deg[i] = 0;
    if (i == 0) {
        const long long* p = (const long long*)ei;
        int is64 = 1;
        for (int j = 0; j < 64; j++) {
            long long v = p[j];
            if (v < 0 || v >= N_NODES) { is64 = 0; break; }
        }
        g_idx64 = is64;
    }
}

__global__ void __launch_bounds__(256) hist_kernel(const void* __restrict__ ei) {
    int e = blockIdx.x * blockDim.x + threadIdx.x;
    if (e >= N_EDGES) return;
    int d = g_idx64 ? (int)((const long long*)ei)[N_EDGES + e]
                    : ((const int*)ei)[N_EDGES + e];
    if ((unsigned)d < N_NODES) atomicAdd(&g_deg[d], 1);
}

// Block-wise exclusive scan of g_deg (512/block); block sums to g_bsum.
__global__ void __launch_bounds__(512) scan1_kernel() {
    __shared__ int sm[512];
    int b = blockIdx.x, t = threadIdx.x;
    int i = b * 512 + t;
    int v = (i < N_NODES) ? g_deg[i] : 0;
    sm[t] = v;
    __syncthreads();
#pragma unroll
    for (int off = 1; off < 512; off <<= 1) {
        int u = (t >= off) ? sm[t - off] : 0;
        __syncthreads();
        sm[t] += u;
        __syncthreads();
    }
    if (i < N_NODES) g_ptr[i] = sm[t] - v;        // exclusive within block
    if (t == 511) g_bsum[b] = sm[511];
}

__global__ void scan2_kernel() {
    if (threadIdx.x == 0 && blockIdx.x == 0) {
        int run = 0;
        for (int b = 0; b < NSCAN_BLK; b++) { g_boff[b] = run; run += g_bsum[b]; }
    }
}

__global__ void __launch_bounds__(512) scan3_kernel() {
    int i = blockIdx.x * 512 + threadIdx.x;
    if (i < N_NODES) {
        int v = g_ptr[i] + g_boff[i >> 9];
        g_ptr[i] = v;
        g_cursor[i] = v;
    }
}

__global__ void __launch_bounds__(256) fill_kernel(const void* __restrict__ ei) {
    int e = blockIdx.x * blockDim.x + threadIdx.x;
    if (e >= N_EDGES) return;
    int s, d;
    if (g_idx64) {
        const long long* p = (const long long*)ei;
        s = (int)p[e]; d = (int)p[N_EDGES + e];
    } else {
        const int* p = (const int*)ei;
        s = p[e]; d = p[N_EDGES + e];
    }
    if ((unsigned)s >= N_NODES || (unsigned)d >= N_NODES) return;
    int pos = atomicAdd(&g_cursor[d], 1);
    g_csr[pos] = s;
}

// ---------------------------------------------------------------------------
// Stage 1: x -> fp16 into the x-half of A (cols 512..1023). Pads zeroed.
// ---------------------------------------------------------------------------
__global__ void __launch_bounds__(128) convertX_kernel(const float* __restrict__ x) {
    int row = blockIdx.x;                        // 0..M_PAD-1
    int c4  = threadIdx.x * 4;                   // 0..508
    float4 v = make_float4(0.f, 0.f, 0.f, 0.f);
    if (row < N_NODES)
        v = __ldg((const float4*)(x + (size_t)row * DIM + c4));
    __half2 a = __floats2half2_rn(v.x, v.y);
    __half2 b = __floats2half2_rn(v.z, v.w);
    *(uint2*)(g_A + (size_t)row * KTOT + 512 + c4) = make_uint2(*(uint32_t*)&a, *(uint32_t*)&b);
}

// ---------------------------------------------------------------------------
// Stage 2: CSR aggregate, gathering fp16 x-rows (L2-resident), fp32 accum,
// write fp16 agg into cols 0..511. 64 threads/row, 8 cols each, 2-way unroll.
// ---------------------------------------------------------------------------
__global__ void __launch_bounds__(64) agg_convert_kernel() {
    int row = blockIdx.x;                        // 0..M_PAD-1
    int c8  = threadIdx.x * 8;                   // 0..504
    float s0[8], s1[8];
#pragma unroll
    for (int j = 0; j < 8; j++) { s0[j] = 0.f; s1[j] = 0.f; }
    if (row < N_NODES) {
        int start = g_ptr[row];
        int deg   = g_deg[row];
        int i = 0;
        for (; i + 2 <= deg; i += 2) {
            int u0 = g_csr[start + i];
            int u1 = g_csr[start + i + 1];
            uint4 h0 = __ldg((const uint4*)(g_A + (size_t)u0 * KTOT + 512 + c8));
            uint4 h1 = __ldg((const uint4*)(g_A + (size_t)u1 * KTOT + 512 + c8));
            const __half2* p0 = (const __half2*)&h0;
            const __half2* p1 = (const __half2*)&h1;
#pragma unroll
            for (int p = 0; p < 4; p++) {
                float2 f0 = __half22float2(p0[p]);
                float2 f1 = __half22float2(p1[p]);
                s0[2 * p] += f0.x; s0[2 * p + 1] += f0.y;
                s1[2 * p] += f1.x; s1[2 * p + 1] += f1.y;
            }
        }
        if (i < deg) {
            int u0 = g_csr[start + i];
            uint4 h0 = __ldg((const uint4*)(g_A + (size_t)u0 * KTOT + 512 + c8));
            const __half2* p0 = (const __half2*)&h0;
#pragma unroll
            for (int p = 0; p < 4; p++) {
                float2 f0 = __half22float2(p0[p]);
                s0[2 * p] += f0.x; s0[2 * p + 1] += f0.y;
            }
        }
#pragma unroll
        for (int j = 0; j < 8; j++) s0[j] += s1[j];
    }
    __half2 o0 = __floats2half2_rn(s0[0], s0[1]);
    __half2 o1 = __floats2half2_rn(s0[2], s0[3]);
    __half2 o2 = __floats2half2_rn(s0[4], s0[5]);
    __half2 o3 = __floats2half2_rn(s0[6], s0[7]);
    uint4 ov = make_uint4(*(uint32_t*)&o0, *(uint32_t*)&o1, *(uint32_t*)&o2, *(uint32_t*)&o3);
    *(uint4*)(g_A + (size_t)row * KTOT + c8) = ov;
}

// B[n][k]: n<512 -> [Wl1 | Wr1], n>=512 -> [Wl2 | Wr2]
__global__ void __launch_bounds__(256) convertB_kernel(
    const float* __restrict__ Wl1, const float* __restrict__ Wr1,
    const float* __restrict__ Wl2, const float* __restrict__ Wr2)
{
    int n  = blockIdx.x;                     // 0..1023
    int c4 = threadIdx.x * 4;
    const float* src = (n < 512) ? ((c4 < 512) ? Wl1 : Wr1)
                                 : ((c4 < 512) ? Wl2 : Wr2);
    float4 v = *(const float4*)(src + (size_t)(n & 511) * DIM + (c4 & 511));
    __half2 a = __floats2half2_rn(v.x, v.y);
    __half2 b = __floats2half2_rn(v.z, v.w);
    *(uint2*)(g_B + (size_t)n * KTOT + c4) = make_uint2(*(uint32_t*)&a, *(uint32_t*)&b);
}

// ---------------------------------------------------------------------------
// fp16 mma.sync GEMM: 128x256 CTA tile, BK=32, 4-stage cp.async,
// register double-buffered ldmatrix fragments.
// 8 warps (2M x 4N), warp tile 64x64.
// ---------------------------------------------------------------------------
#define BK 32
#define AROW 80
#define A_SM (128 * AROW)               // 10240 B
#define B_SM (256 * AROW)               // 20480 B
#define BUF_SZ (A_SM + B_SM)            // 30720 B
#define NSTAGE 4
#define SMEM_DYN (NSTAGE * BUF_SZ)      // 122880 B
#define NK (KTOT / BK)                  // 32

__global__ void __launch_bounds__(256, 1)
gemm_mma_kernel(const float* __restrict__ bl1, const float* __restrict__ bl2,
                float* __restrict__ out)
{
    extern __shared__ __align__(16) char dsmem[];
    __shared__ float bias_s[256];

    const int tid  = threadIdx.x;
    const int wid  = tid >> 5;
    const int lane = tid & 31;
    const int m0   = blockIdx.y * 128;
    const int n0   = blockIdx.x * 256;      // 0,256,512,768
    const bool isScale = (n0 >= 512);
    const int nLoc = n0 & 511;              // 0 or 256

    if (tid < 256) bias_s[tid] = (isScale ? bl2 : bl1)[nLoc + tid];

    const uint32_t sbase = smem_u32(dsmem);
    const __half* srcA = g_A + (size_t)m0 * KTOT;
    const __half* srcB = g_B + (size_t)n0 * KTOT;

    auto load_stage = [&](int kt, int buf) {
        const int k0 = kt * BK;
        uint32_t bbase = sbase + buf * BUF_SZ;
#pragma unroll
        for (int i = 0; i < 6; ++i) {
            int id = tid + (i << 8);            // 0..1535
            if (id < 512) {
                int row = id >> 2, c16 = id & 3;
                cp16(bbase + row * AROW + c16 * 16,
                     srcA + (size_t)row * KTOT + k0 + c16 * 8);
            } else {
                int loc = id - 512;
                int row = loc >> 2, c16 = loc & 3;
                cp16(bbase + A_SM + row * AROW + c16 * 16,
                     srcB + (size_t)row * KTOT + k0 + c16 * 8);
            }
        }
        cp_commit();
    };

    const int mw = (wid & 1) * 64;          // warp M offset
    const int nw = (wid >> 1) * 64;         // warp N offset

    float acc[4][8][4];
#pragma unroll
    for (int mt = 0; mt < 4; mt++)
#pragma unroll
        for (int nt = 0; nt < 8; nt++)
#pragma unroll
            for (int r = 0; r < 4; r++) acc[mt][nt][r] = 0.f;

    load_stage(0, 0);
    load_stage(1, 1);
    load_stage(2, 2);

    const int aRowOff = (lane & 15);
    const int aColB   = (lane >> 4) << 4;
    const int bRowOff = (lane & 7) + ((lane >> 4) << 3);
    const int bColB   = ((lane >> 3) & 1) << 4;

    uint32_t af[2][4][4], bf[2][4][4];

    auto load_frags = [&](uint32_t bbase, int ks, int slot) {
        const int kb = ks * 32;
#pragma unroll
        for (int mt = 0; mt < 4; mt++)
            ldsm4(af[slot][mt], bbase + (mw + mt * 16 + aRowOff) * AROW + kb + aColB);
#pragma unroll
        for (int np = 0; np < 4; np++)
            ldsm4(bf[slot][np], bbase + A_SM
                          + (nw + np * 16 + bRowOff) * AROW + kb + bColB);
    };

    int buf = 0;
    for (int kt = 0; kt < NK; ++kt) {
        cp_wait<2>();
        __syncthreads();

        const uint32_t bbase = sbase + buf * BUF_SZ;
        load_frags(bbase, 0, 0);
#pragma unroll
        for (int ks = 0; ks < 2; ++ks) {
            if (ks == 0) load_frags(bbase, 1, 1);   // prefetch while mma issues
#pragma unroll
            for (int mt = 0; mt < 4; mt++)
#pragma unroll
                for (int nt = 0; nt < 8; nt++)
                    mma_f16(acc[mt][nt], af[ks][mt], &bf[ks][nt >> 1][(nt & 1) * 2]);
        }
        if (kt + 3 < NK) load_stage(kt + 3, (kt + 3) % NSTAGE);
        buf = (buf + 1) % NSTAGE;
    }

    // ---- epilogue -----------------------------------------------------------
    const int rq = lane >> 2;
    const int cq = (lane & 3) * 2;
#pragma unroll
    for (int mt = 0; mt < 4; mt++) {
        int r0 = m0 + mw + mt * 16 + rq;
#pragma unroll
        for (int half = 0; half < 2; half++) {
            int m = r0 + half * 8;
            if (m >= N_NODES) continue;
            float* op = out + (isScale ? SCALE_OFF : 0) + (size_t)m * DIM + nLoc;
#pragma unroll
            for (int nt = 0; nt < 8; nt++) {
                int cl = nw + nt * 8 + cq;
                float v0 = acc[mt][nt][half * 2 + 0] + bias_s[cl];
                float v1 = acc[mt][nt][half * 2 + 1] + bias_s[cl + 1];
                if (!isScale) {
                    v0 = fminf(fmaxf(v0, -100.f), 100.f);
                    v1 = fminf(fmaxf(v1, -100.f), 100.f);
                } else {
                    v0 = fminf(fmaxf(v0, 0.f) + log1pf(expf(-fabsf(v0))) + 0.001f, 100.f);
                    v1 = fminf(fmaxf(v1, 0.f) + log1pf(expf(-fabsf(v1))) + 0.001f, 100.f);
                }
                *(float2*)(op + cl) = make_float2(v0, v1);
            }
        }
    }
}

// ---------------------------------------------------------------------------
extern "C" void kernel_launch(void* const* d_in, const int* in_sizes, int n_in,
                              void* d_out, int out_size)
{
    const float* x = 0;
    const void*  ei = 0;
    const float* Ws[4]; int nW = 0; int wpos[4];
    const float* bs[2]; int nb = 0; int bpos[2];
    for (int i = 0; i < n_in; i++) {
        int sz = in_sizes[i];
        if (sz == N_NODES * DIM)      x = (const float*)d_in[i];
        else if (sz == 2 * N_EDGES)   ei = d_in[i];
        else if (sz == DIM * DIM) { if (nW < 4) { wpos[nW] = i; Ws[nW++] = (const float*)d_in[i]; } }
        else if (sz == DIM)       { if (nb < 2) { bpos[nb] = i; bs[nb++] = (const float*)d_in[i]; } }
    }
    const float *Wl1, *Wr1, *Wl2, *Wr2, *bl1, *bl2;
    bl1 = bs[0]; bl2 = bs[1];
    if (nb == 2 && nW == 4 && bpos[0] < wpos[1]) {
        Wl1 = Ws[0]; Wr1 = Ws[1]; Wl2 = Ws[2]; Wr2 = Ws[3];   // dict order
    } else {
        Wl1 = Ws[0]; Wl2 = Ws[1]; Wr1 = Ws[2]; Wr2 = Ws[3];   // alphabetical
    }
    float* out = (float*)d_out;

    static int smem_set = 0;
    if (!smem_set) {
        cudaFuncSetAttribute(gemm_mma_kernel,
                             cudaFuncAttributeMaxDynamicSharedMemorySize, SMEM_DYN);
        smem_set = 1;
    }

    zero_detect_kernel<<<49, 1024>>>(ei);
    hist_kernel<<<3125, 256>>>(ei);
    scan1_kernel<<<NSCAN_BLK, 512>>>();
    scan2_kernel<<<1, 32>>>();
    scan3_kernel<<<NSCAN_BLK, 512>>>();
    fill_kernel<<<3125, 256>>>(ei);
    convertX_kernel<<<M_PAD, 128>>>(x);
    agg_convert_kernel<<<M_PAD, 64>>>();
    convertB_kernel<<<1024, 256>>>(Wl1, Wr1, Wl2, Wr2);
    gemm_mma_kernel<<<dim3(4, 391), 256, SMEM_DYN>>>(bl1, bl2, out);
}